// round 4
// baseline (speedup 1.0000x reference)
#include <cuda_runtime.h>

#define BB 8
#define HH 512
#define WW 512
#define HW (HH * WW)

#define TX 32
#define PY 8
#define TYW 4
#define TILE_H (PY * TYW)     // 32
#define SW (TX + 6)           // 38
#define SH (TILE_H + 6)       // 38
#define NBLOCKS ((WW / TX) * (HH / TILE_H) * BB)  // 2048

__device__ int g_total = 0;
__device__ unsigned int g_done = 0;

__global__ __launch_bounds__(TX * TYW)
void census_fused(const float* __restrict__ pred, const float* __restrict__ tgt,
                  float* __restrict__ out) {
    __shared__ float sp[SH][SW];
    __shared__ float st[SH][SW];
    __shared__ int wsum[TYW];

    const int b  = blockIdx.z;
    const int x0 = blockIdx.x * TX;
    const int y0 = blockIdx.y * TILE_H;
    const int tid = threadIdx.y * TX + threadIdx.x;

    const float* __restrict__ pb = pred + (size_t)b * 3 * HW;
    const float* __restrict__ tb = tgt  + (size_t)b * 3 * HW;

    // Halo load + fused RGB->gray, reflect padding (no edge repeat)
    for (int idx = tid; idx < SH * SW; idx += TX * TYW) {
        int ly = idx / SW;
        int lx = idx - ly * SW;
        int gy = y0 + ly - 3;
        gy = (gy < 0) ? -gy : ((gy >= HH) ? 2 * HH - 2 - gy : gy);
        int gx = x0 + lx - 3;
        gx = (gx < 0) ? -gx : ((gx >= WW) ? 2 * WW - 2 - gx : gx);
        int off = gy * WW + gx;
        float r = pb[off], g = pb[HW + off], bl = pb[2 * HW + off];
        sp[ly][lx] = fmaf(0.299f, r, fmaf(0.587f, g, 0.114f * bl));
        r = tb[off]; g = tb[HW + off]; bl = tb[2 * HW + off];
        st[ly][lx] = fmaf(0.299f, r, fmaf(0.587f, g, 0.114f * bl));
    }
    __syncthreads();

    const int tx   = threadIdx.x;
    const int base = threadIdx.y * PY;

    float cp[PY], ct[PY];
#pragma unroll
    for (int k = 0; k < PY; k++) {
        cp[k] = sp[base + k + 3][tx + 3];
        ct[k] = st[base + k + 3][tx + 3];
    }

    // Fast path: 24 FORWARD offsets only (dy>0, or dy==0 && dx>0), counted x2.
    int cnt = 0;
#pragma unroll
    for (int r = 3; r <= 13; r++) {                 // 11 window rows
        float vp[7], vt[7];
#pragma unroll
        for (int j = 0; j < 7; j++) {
            vp[j] = sp[base + r][tx + j];
            vt[j] = st[base + r][tx + j];
        }
        // dy == 0: center row k = r-3, dx = 1..3  (j = 4..6)
        {
            const int k = r - 3;
            if (k < PY) {
#pragma unroll
                for (int j = 4; j < 7; j++)
                    cnt += ((cp[k] > vp[j]) != (ct[k] > vt[j])) ? 1 : 0;
            }
        }
        // dy = 1..3: k = r-3-dy, all 7 columns
#pragma unroll
        for (int dy = 1; dy <= 3; dy++) {
            const int k = r - 3 - dy;
            if (k >= 0 && k < PY) {
#pragma unroll
                for (int j = 0; j < 7; j++)
                    cnt += ((cp[k] > vp[j]) != (ct[k] > vt[j])) ? 1 : 0;
            }
        }
    }

    int total = 2 * cnt;

    // Boundary correction: M = 2S + sum_{BWD,out} m - sum_{FWD,out} m.
    // Only pixels within 3 of the image border have out-of-image offsets.
    if (blockIdx.x == 0 || blockIdx.x == gridDim.x - 1 ||
        blockIdx.y == 0 || blockIdx.y == gridDim.y - 1) {
        const int px = x0 + tx;
#pragma unroll 1
        for (int k = 0; k < PY; k++) {
            const int py = y0 + base + k;
            if (px < 3 || px >= WW - 3 || py < 3 || py >= HH - 3) {
#pragma unroll 1
                for (int dy = -3; dy <= 3; dy++) {
#pragma unroll 1
                    for (int dx = -3; dx <= 3; dx++) {
                        if (dy == 0 && dx == 0) continue;
                        int ny = py + dy, nx = px + dx;
                        if (ny >= 0 && ny < HH && nx >= 0 && nx < WW) continue; // in-image: no correction
                        float np = sp[base + 3 + k + dy][tx + 3 + dx];
                        float nt = st[base + 3 + k + dy][tx + 3 + dx];
                        int m = ((cp[k] > np) != (ct[k] > nt)) ? 1 : 0;
                        bool bwd = (dy < 0) || (dy == 0 && dx < 0);
                        total += bwd ? m : -m;
                    }
                }
            }
        }
    }

    // Block reduction
#pragma unroll
    for (int o = 16; o > 0; o >>= 1)
        total += __shfl_down_sync(0xffffffffu, total, o);
    if (tx == 0) wsum[threadIdx.y] = total;
    __syncthreads();

    if (tid == 0) {
        int v = wsum[0] + wsum[1] + wsum[2] + wsum[3];
        atomicAdd(&g_total, v);
        __threadfence();
        unsigned int ticket = atomicAdd(&g_done, 1u);
        if (ticket == NBLOCKS - 1) {
            int tot = atomicAdd(&g_total, 0);
            const double denom = 48.0 * (double)BB * (double)HW; // 100663296
            out[0] = (float)((double)tot / denom);
            atomicExch(&g_total, 0);      // reset for next graph replay
            atomicExch(&g_done, 0u);
        }
    }
}

extern "C" void kernel_launch(void* const* d_in, const int* in_sizes, int n_in,
                              void* d_out, int out_size) {
    const float* pred = (const float*)d_in[0];
    const float* tgt  = (const float*)d_in[1];
    float* out = (float*)d_out;
    (void)in_sizes; (void)n_in; (void)out_size;

    dim3 bdim(TX, TYW);
    dim3 gdim(WW / TX, HH / TILE_H, BB);
    census_fused<<<gdim, bdim>>>(pred, tgt, out);
}

// round 5
// speedup vs baseline: 1.8867x; 1.8867x over previous
#include <cuda_runtime.h>

#define BB 8
#define HH 512
#define WW 512
#define HW (HH * WW)

#define TX 32
#define PY 8
#define TYW 4
#define TILE_H (PY * TYW)   // 32
#define SW (TX + 6)         // 38
#define SH (TILE_H + 6)     // 38
#define NBLOCKS ((WW / TX) * (HH / TILE_H) * BB)  // 2048

__device__ int g_total = 0;
__device__ unsigned int g_done = 0;

__global__ __launch_bounds__(TX * TYW)
void census_fused(const float* __restrict__ pred, const float* __restrict__ tgt,
                  float* __restrict__ out) {
    __shared__ float2 s[SH][SW];      // (pred_gray, tgt_gray) interleaved
    __shared__ int wsum[TYW];

    const int b  = blockIdx.z;
    const int x0 = blockIdx.x * TX;
    const int y0 = blockIdx.y * TILE_H;
    const int tid = threadIdx.y * TX + threadIdx.x;

    const float* __restrict__ pb = pred + (size_t)b * 3 * HW;
    const float* __restrict__ tb = tgt  + (size_t)b * 3 * HW;

    // Halo load + fused RGB->gray, reflect padding (no edge repeat)
    for (int idx = tid; idx < SH * SW; idx += TX * TYW) {
        int ly = idx / SW;
        int lx = idx - ly * SW;
        int gy = y0 + ly - 3;
        gy = (gy < 0) ? -gy : ((gy >= HH) ? 2 * HH - 2 - gy : gy);
        int gx = x0 + lx - 3;
        gx = (gx < 0) ? -gx : ((gx >= WW) ? 2 * WW - 2 - gx : gx);
        int off = gy * WW + gx;
        float2 v;
        v.x = fmaf(0.299f, pb[off], fmaf(0.587f, pb[HW + off], 0.114f * pb[2 * HW + off]));
        v.y = fmaf(0.299f, tb[off], fmaf(0.587f, tb[HW + off], 0.114f * tb[2 * HW + off]));
        s[ly][lx] = v;
    }
    __syncthreads();

    const int tx   = threadIdx.x;
    const int base = threadIdx.y * PY;

    float cp[PY], ct[PY];
#pragma unroll
    for (int k = 0; k < PY; k++) {
        float2 c = s[base + k + 3][tx + 3];
        cp[k] = c.x; ct[k] = c.y;
    }

    int total;
    const bool interiorBlk = (blockIdx.x > 0 && blockIdx.x + 1 < gridDim.x &&
                              blockIdx.y > 0 && blockIdx.y + 1 < gridDim.y);
    if (interiorBlk) {
        // All pixels >=3 from image border: 24 forward offsets, counted x2.
        int cnt = 0;
#pragma unroll
        for (int r = 3; r <= 13; r++) {
            float2 v[7];
#pragma unroll
            for (int j = 0; j < 7; j++) v[j] = s[base + r][tx + j];
            {   // dy == 0, dx = 1..3
                const int k = r - 3;
                if (k < PY) {
#pragma unroll
                    for (int j = 4; j < 7; j++)
                        cnt += ((cp[k] > v[j].x) != (ct[k] > v[j].y)) ? 1 : 0;
                }
            }
#pragma unroll
            for (int dy = 1; dy <= 3; dy++) {   // dy = 1..3, all dx
                const int k = r - 3 - dy;
                if (k >= 0 && k < PY) {
#pragma unroll
                    for (int j = 0; j < 7; j++)
                        cnt += ((cp[k] > v[j].x) != (ct[k] > v[j].y)) ? 1 : 0;
                }
            }
        }
        total = 2 * cnt;
    } else {
        // Weighted exact path (uniform, branch-free):
        //   target in-image : fwd x2, bwd x0
        //   target out      : x1 (reflected value already in smem)
        int ox[7];
#pragma unroll
        for (int j = 0; j < 7; j++)
            ox[j] = ((unsigned)(x0 + tx + j - 3) >= WW) ? 1 : 0;

        int cnt = 0;
#pragma unroll
        for (int r = 0; r < 14; r++) {
            const int oy = ((unsigned)(y0 + base + r - 3) >= HH) ? 1 : 0;
            float2 v[7];
            int wf[7], wb[7];
#pragma unroll
            for (int j = 0; j < 7; j++) {
                v[j] = s[base + r][tx + j];
                int o = oy | ox[j];
                wf[j] = 2 - o;   // forward weight
                wb[j] = o;       // backward weight
            }
#pragma unroll
            for (int k = 0; k < PY; k++) {
                const int dy = r - 3 - k;
                if (dy < -3 || dy > 3) continue;   // compile-time pruned
#pragma unroll
                for (int j = 0; j < 7; j++) {
                    const int dx = j - 3;
                    if (dy == 0 && dx == 0) continue;
                    int m = ((cp[k] > v[j].x) != (ct[k] > v[j].y)) ? 1 : 0;
                    const bool fwd = (dy > 0) || (dy == 0 && dx > 0);
                    cnt += m * (fwd ? wf[j] : wb[j]);
                }
            }
        }
        total = cnt;
    }

    // Block reduction
#pragma unroll
    for (int o = 16; o > 0; o >>= 1)
        total += __shfl_down_sync(0xffffffffu, total, o);
    if (tx == 0) wsum[threadIdx.y] = total;
    __syncthreads();

    if (tid == 0) {
        int v = wsum[0] + wsum[1] + wsum[2] + wsum[3];
        atomicAdd(&g_total, v);
        __threadfence();
        unsigned int ticket = atomicAdd(&g_done, 1u);
        if (ticket == NBLOCKS - 1) {
            int tot = atomicAdd(&g_total, 0);
            const double denom = 48.0 * (double)BB * (double)HW; // 100663296
            out[0] = (float)((double)tot / denom);
            atomicExch(&g_total, 0);      // reset for next graph replay
            atomicExch(&g_done, 0u);
        }
    }
}

extern "C" void kernel_launch(void* const* d_in, const int* in_sizes, int n_in,
                              void* d_out, int out_size) {
    const float* pred = (const float*)d_in[0];
    const float* tgt  = (const float*)d_in[1];
    float* out = (float*)d_out;
    (void)in_sizes; (void)n_in; (void)out_size;

    dim3 bdim(TX, TYW);
    dim3 gdim(WW / TX, HH / TILE_H, BB);
    census_fused<<<gdim, bdim>>>(pred, tgt, out);
}